// round 2
// baseline (speedup 1.0000x reference)
#include <cuda_runtime.h>

#define THREADS 256
#define NBINS 16

// Per-block partial sums of info_gain (written, not atomically accumulated ->
// deterministic across graph replays). 32768 >= max grid size we launch.
__device__ float g_partials[32768];

__global__ void __launch_bounds__(THREADS) ep_main_kernel(
    const float* __restrict__ obs,      // (rows, dim)
    const float* __restrict__ counts,   // (dim, 16)
    float* __restrict__ out,            // concatenated outputs
    int dim, int rows, float inv_rows)
{
    const int i = blockIdx.x * THREADS + threadIdx.x;
    float ig = 0.0f;

    if (i < dim) {
        // ---- mean over observation rows (coalesced column loads) ----
        float m = 0.0f;
        #pragma unroll 8
        for (int r = 0; r < rows; ++r)
            m += obs[(size_t)r * dim + i];
        m *= inv_rows;

        // ---- sigmoid binning ----
        float sgm = 1.0f / (1.0f + expf(-m));
        int b = (int)(sgm * (float)(NBINS - 1));
        b = b < 0 ? 0 : (b > NBINS - 1 ? NBINS - 1 : b);

        // ---- load counts row (4 x LDG.128) ----
        const float4* crow = (const float4*)(counts + (size_t)i * NBINS);
        float4 v0 = crow[0], v1 = crow[1], v2 = crow[2], v3 = crow[3];
        float c[NBINS] = { v0.x, v0.y, v0.z, v0.w,
                           v1.x, v1.y, v1.z, v1.w,
                           v2.x, v2.y, v2.z, v2.w,
                           v3.x, v3.y, v3.z, v3.w };

        float s = 0.0f;
        #pragma unroll
        for (int j = 0; j < NBINS; ++j) s += c[j];

        float inv  = 1.0f / fmaxf(s,        1e-8f);
        float invp = 1.0f / fmaxf(s + 1.0f, 1e-8f);

        float Hp = 0.0f, Hq = 0.0f;
        float nc[NBINS];
        #pragma unroll
        for (int j = 0; j < NBINS; ++j) {
            float oh = (j == b) ? 1.0f : 0.0f;
            float p  = c[j] * inv;
            float pp = (c[j] + oh) * invp;
            float lp = __log2f(p  + 1e-10f);
            float lq = __log2f(pp + 1e-10f);
            Hp -= p  * lp;
            Hq -= pp * lq;
            ig += pp * (lq - lp);
            nc[j] = fmaxf(c[j] * 0.95f + oh * 0.05f, 0.01f);
        }
        ig = fmaxf(ig, 0.0f);

        // ---- outputs: info_gain | mean(1) | H_prior | H_post | epi(1) | new_counts ----
        out[i] = ig;
        out[(size_t)dim     + 1 + i] = Hp;
        out[(size_t)2 * dim + 1 + i] = Hq;

        // new_belief_counts base offset (3*dim + 2) is 8B-aligned -> float2 stores
        float2* nrow = (float2*)(out + (size_t)3 * dim + 2 + (size_t)i * NBINS);
        #pragma unroll
        for (int j = 0; j < 8; ++j)
            nrow[j] = make_float2(nc[2 * j], nc[2 * j + 1]);
    }

    // ---- deterministic block reduction of info_gain ----
    const unsigned FULL = 0xffffffffu;
    #pragma unroll
    for (int o = 16; o > 0; o >>= 1)
        ig += __shfl_down_sync(FULL, ig, o);

    __shared__ float ws[THREADS / 32];
    int lane = threadIdx.x & 31;
    int w    = threadIdx.x >> 5;
    if (lane == 0) ws[w] = ig;
    __syncthreads();
    if (w == 0) {
        float v = (lane < THREADS / 32) ? ws[lane] : 0.0f;
        #pragma unroll
        for (int o = 4; o > 0; o >>= 1)
            v += __shfl_down_sync(FULL, v, o);
        if (lane == 0) g_partials[blockIdx.x] = v;
    }
}

__global__ void __launch_bounds__(256) ep_finalize_kernel(
    float* __restrict__ out, int dim, int nblocks)
{
    __shared__ double sh[256];
    double a = 0.0;
    // fixed strided order -> deterministic
    for (int t = threadIdx.x; t < nblocks; t += 256)
        a += (double)g_partials[t];
    sh[threadIdx.x] = a;
    __syncthreads();
    #pragma unroll
    for (int o = 128; o > 0; o >>= 1) {
        if (threadIdx.x < o) sh[threadIdx.x] += sh[threadIdx.x + o];
        __syncthreads();
    }
    if (threadIdx.x == 0) {
        float mean = (float)(sh[0] / (double)dim);
        out[dim] = mean;
        float z = mean * 50.0f - 1.0f;
        out[(size_t)3 * dim + 1] = 1.0f / (1.0f + expf(-z));
    }
}

extern "C" void kernel_launch(void* const* d_in, const int* in_sizes, int n_in,
                              void* d_out, int out_size)
{
    const float* obs    = (const float*)d_in[0];
    const float* counts = (const float*)d_in[1];
    float* out = (float*)d_out;

    int dim  = in_sizes[1] / NBINS;
    int rows = in_sizes[0] / dim;
    int nb   = (dim + THREADS - 1) / THREADS;

    ep_main_kernel<<<nb, THREADS>>>(obs, counts, out, dim, rows, 1.0f / (float)rows);
    ep_finalize_kernel<<<1, 256>>>(out, dim, nb);
}

// round 3
// speedup vs baseline: 1.2526x; 1.2526x over previous
#include <cuda_runtime.h>

#define THREADS 256
#define NBINS 16

// Per-block partials + ticket counter for single-kernel last-block reduction.
// Counter is reset to 0 by the last block each run -> deterministic across
// graph replays.
__device__ float g_partials[32768];
__device__ unsigned int g_counter = 0;

__global__ void __launch_bounds__(THREADS) ep_fused_kernel(
    const float* __restrict__ obs,      // (rows, dim)
    const float* __restrict__ counts,   // (dim, 16)
    float* __restrict__ out,            // concatenated outputs
    int dim, int rows, float inv_rows, int nblocks)
{
    // Padded staging: each local dim d owns float4 slots [d*5, d*5+4); slot
    // d*5+4 is padding (makes per-row LDS.128/STS.128 bank-conflict-free).
    __shared__ float4 s4[THREADS * 5];
    float2* s2 = (float2*)s4;

    const int t    = threadIdx.x;
    const int base = blockIdx.x * THREADS;
    const int i    = base + t;
    const bool full = (base + THREADS <= dim);   // uniform per block

    float ig = 0.0f;

    if (full) {
        // ---- stage counts in: coalesced float4 loads -> padded smem ----
        const float4* cin = (const float4*)counts + (size_t)base * 4;
        #pragma unroll
        for (int k = 0; k < 4; ++k) {
            int idx = t + k * THREADS;                 // [0, 1024)
            s4[(idx >> 2) * 5 + (idx & 3)] = cin[idx];
        }
        __syncthreads();

        // ---- mean over observation rows (coalesced) ----
        float m = 0.0f;
        #pragma unroll 8
        for (int r = 0; r < rows; ++r)
            m += obs[(size_t)r * dim + i];
        m *= inv_rows;

        float sgm = 1.0f / (1.0f + expf(-m));
        int b = (int)(sgm * (float)(NBINS - 1));
        b = b < 0 ? 0 : (b > NBINS - 1 ? NBINS - 1 : b);

        // ---- read own row from smem (conflict-free) ----
        float c[NBINS];
        #pragma unroll
        for (int q = 0; q < 4; ++q) {
            float4 v = s4[t * 5 + q];
            c[4*q+0] = v.x; c[4*q+1] = v.y; c[4*q+2] = v.z; c[4*q+3] = v.w;
        }

        float s = 0.0f;
        #pragma unroll
        for (int j = 0; j < NBINS; ++j) s += c[j];
        float inv  = 1.0f / fmaxf(s,        1e-8f);
        float invp = 1.0f / fmaxf(s + 1.0f, 1e-8f);

        float Hp = 0.0f, Hq = 0.0f;
        float nc[NBINS];
        #pragma unroll
        for (int j = 0; j < NBINS; ++j) {
            float oh = (j == b) ? 1.0f : 0.0f;
            float p  = c[j] * inv;
            float pp = (c[j] + oh) * invp;
            float lp = __log2f(p  + 1e-10f);
            float lq = __log2f(pp + 1e-10f);
            Hp -= p  * lp;
            Hq -= pp * lq;
            ig += pp * (lq - lp);
            nc[j] = fmaxf(c[j] * 0.95f + oh * 0.05f, 0.01f);
        }
        ig = fmaxf(ig, 0.0f);

        out[i] = ig;
        out[(size_t)dim     + 1 + i] = Hp;
        out[(size_t)2 * dim + 1 + i] = Hq;

        // ---- write nc back to OWN smem row (no cross-thread hazard) ----
        #pragma unroll
        for (int q = 0; q < 4; ++q)
            s4[t * 5 + q] = make_float4(nc[4*q], nc[4*q+1], nc[4*q+2], nc[4*q+3]);
        __syncthreads();

        // ---- coalesced float2 stores (output rows only 8B-aligned) ----
        float2* obase = (float2*)(out + (size_t)3 * dim + 2 + (size_t)base * NBINS);
        #pragma unroll
        for (int k = 0; k < 8; ++k) {
            int idx = t + k * THREADS;                 // float2 idx [0, 2048)
            int d = idx >> 3, h = idx & 7;
            obase[idx] = s2[d * 10 + h];
        }
    } else if (i < dim) {
        // ---- scalar tail path (not taken for dim % 256 == 0) ----
        float m = 0.0f;
        for (int r = 0; r < rows; ++r) m += obs[(size_t)r * dim + i];
        m *= inv_rows;
        float sgm = 1.0f / (1.0f + expf(-m));
        int b = (int)(sgm * (float)(NBINS - 1));
        b = b < 0 ? 0 : (b > NBINS - 1 ? NBINS - 1 : b);

        float c[NBINS];
        #pragma unroll
        for (int j = 0; j < NBINS; ++j) c[j] = counts[(size_t)i * NBINS + j];
        float s = 0.0f;
        #pragma unroll
        for (int j = 0; j < NBINS; ++j) s += c[j];
        float inv  = 1.0f / fmaxf(s,        1e-8f);
        float invp = 1.0f / fmaxf(s + 1.0f, 1e-8f);
        float Hp = 0.0f, Hq = 0.0f;
        #pragma unroll
        for (int j = 0; j < NBINS; ++j) {
            float oh = (j == b) ? 1.0f : 0.0f;
            float p  = c[j] * inv;
            float pp = (c[j] + oh) * invp;
            float lp = __log2f(p  + 1e-10f);
            float lq = __log2f(pp + 1e-10f);
            Hp -= p * lp; Hq -= pp * lq;
            ig += pp * (lq - lp);
            out[(size_t)3 * dim + 2 + (size_t)i * NBINS + j] =
                fmaxf(c[j] * 0.95f + oh * 0.05f, 0.01f);
        }
        ig = fmaxf(ig, 0.0f);
        out[i] = ig;
        out[(size_t)dim     + 1 + i] = Hp;
        out[(size_t)2 * dim + 1 + i] = Hq;
    }

    // ---- deterministic block reduction of info_gain ----
    const unsigned FULL_M = 0xffffffffu;
    #pragma unroll
    for (int o = 16; o > 0; o >>= 1)
        ig += __shfl_down_sync(FULL_M, ig, o);

    __shared__ float ws[THREADS / 32];
    int lane = threadIdx.x & 31;
    int w    = threadIdx.x >> 5;
    if (lane == 0) ws[w] = ig;
    __syncthreads();
    if (w == 0) {
        float v = (lane < THREADS / 32) ? ws[lane] : 0.0f;
        #pragma unroll
        for (int o = 4; o > 0; o >>= 1)
            v += __shfl_down_sync(FULL_M, v, o);
        if (lane == 0) g_partials[blockIdx.x] = v;
    }

    // ---- last-block final reduction (replaces second kernel) ----
    __shared__ bool is_last;
    __threadfence();
    if (threadIdx.x == 0) {
        unsigned ticket = atomicAdd(&g_counter, 1u);
        is_last = (ticket == (unsigned)(nblocks - 1));
    }
    __syncthreads();

    if (is_last) {
        __threadfence();  // acquire: see all blocks' partials
        __shared__ double sh[THREADS];
        double a = 0.0;
        for (int p = threadIdx.x; p < nblocks; p += THREADS)   // fixed order
            a += (double)g_partials[p];
        sh[threadIdx.x] = a;
        __syncthreads();
        #pragma unroll
        for (int o = THREADS / 2; o > 0; o >>= 1) {
            if (threadIdx.x < o) sh[threadIdx.x] += sh[threadIdx.x + o];
            __syncthreads();
        }
        if (threadIdx.x == 0) {
            float mean = (float)(sh[0] / (double)dim);
            out[dim] = mean;
            float z = mean * 50.0f - 1.0f;
            out[(size_t)3 * dim + 1] = 1.0f / (1.0f + expf(-z));
            g_counter = 0;   // reset for next graph replay
        }
    }
}

extern "C" void kernel_launch(void* const* d_in, const int* in_sizes, int n_in,
                              void* d_out, int out_size)
{
    const float* obs    = (const float*)d_in[0];
    const float* counts = (const float*)d_in[1];
    float* out = (float*)d_out;

    int dim  = in_sizes[1] / NBINS;
    int rows = in_sizes[0] / dim;
    int nb   = (dim + THREADS - 1) / THREADS;

    ep_fused_kernel<<<nb, THREADS>>>(obs, counts, out, dim, rows,
                                     1.0f / (float)rows, nb);
}

// round 4
// speedup vs baseline: 1.3395x; 1.0693x over previous
#include <cuda_runtime.h>

#define THREADS 256
#define NBINS 16

__device__ float g_partials[32768];
__device__ unsigned int g_counter = 0;

__global__ void __launch_bounds__(THREADS) ep_fused_kernel(
    const float* __restrict__ obs,      // (rows, dim)
    const float* __restrict__ counts,   // (dim, 16)
    float* __restrict__ out,            // concatenated outputs
    int dim, int rows, float inv_rows, int nblocks)
{
    // Padded staging: local dim d owns float4 slots [d*5, d*5+4); slot d*5+4
    // is padding (conflict-free LDS.128 per-row reads).
    __shared__ float4 s4[THREADS * 5];
    __shared__ int    sb[THREADS];          // bin index per local dim
    float2* s2 = (float2*)s4;

    const int t    = threadIdx.x;
    const int base = blockIdx.x * THREADS;
    const int i    = base + t;
    const bool full = (base + THREADS <= dim);   // uniform per block

    float ig = 0.0f;

    if (full) {
        // ---- stage counts: coalesced float4 streaming loads -> padded smem ----
        const float4* cin = (const float4*)counts + (size_t)base * 4;
        #pragma unroll
        for (int k = 0; k < 4; ++k) {
            int idx = t + k * THREADS;                 // [0, 1024)
            s4[(idx >> 2) * 5 + (idx & 3)] = __ldcs(cin + idx);
        }
        __syncthreads();

        // ---- mean over observation rows (coalesced, streaming) ----
        float m = 0.0f;
        const float* op = obs + i;
        #pragma unroll 8
        for (int r = 0; r < rows; ++r)
            m += __ldcs(op + (size_t)r * dim);
        m *= inv_rows;

        float sgm = 1.0f / (1.0f + expf(-m));
        int b = (int)(sgm * (float)(NBINS - 1));
        b = b < 0 ? 0 : (b > NBINS - 1 ? NBINS - 1 : b);
        sb[t] = b;

        // ---- own counts row from smem (conflict-free) ----
        float c[NBINS];
        #pragma unroll
        for (int q = 0; q < 4; ++q) {
            float4 v = s4[t * 5 + q];
            c[4*q+0] = v.x; c[4*q+1] = v.y; c[4*q+2] = v.z; c[4*q+3] = v.w;
        }

        float s = 0.0f;
        #pragma unroll
        for (int j = 0; j < NBINS; ++j) s += c[j];

        // Exact decomposition: log2(c/s + 1e-10) = log2(c + 1e-10*s) - log2(s)
        const float tiny = 1e-10f * s;
        float T = 0.0f, cb = 0.0f, ubin = 0.0f;
        #pragma unroll
        for (int j = 0; j < NBINS; ++j) {
            float u = __log2f(c[j] + tiny);
            T += c[j] * u;
            if (j == b) { cb = c[j]; ubin = u; }
        }
        float ub  = __log2f(cb + 1.0f);
        float ls  = __log2f(s);
        float ls1 = __log2f(s + 1.0f);
        float inv  = 1.0f / s;
        float invp = 1.0f / (s + 1.0f);

        float Hp = ls  - T * inv;
        float Hq = ls1 - (T - cb * ubin + (cb + 1.0f) * ub) * invp;
        ig = fmaxf((cb + 1.0f) * invp * (ub - ubin) - (ls1 - ls), 0.0f);

        __stcs(out + i, ig);
        __stcs(out + (size_t)dim     + 1 + i, Hp);
        __stcs(out + (size_t)2 * dim + 1 + i, Hq);

        __syncthreads();   // sb[] visible to whole block

        // ---- coalesced new_counts stores, recomputed from input staging ----
        float2* obase = (float2*)(out + (size_t)3 * dim + 2 + (size_t)base * NBINS);
        #pragma unroll
        for (int k = 0; k < 8; ++k) {
            int idx = t + k * THREADS;                 // float2 idx [0, 2048)
            int d = idx >> 3, h = idx & 7;
            float2 cc = s2[d * 10 + h];
            int bd = sb[d];
            float o0 = (2 * h     == bd) ? 0.05f : 0.0f;
            float o1 = (2 * h + 1 == bd) ? 0.05f : 0.0f;
            float2 r;
            r.x = fmaxf(cc.x * 0.95f + o0, 0.01f);
            r.y = fmaxf(cc.y * 0.95f + o1, 0.01f);
            __stcs(obase + idx, r);
        }
    } else if (i < dim) {
        // ---- scalar tail (not taken when dim % 256 == 0) ----
        float m = 0.0f;
        for (int r = 0; r < rows; ++r) m += obs[(size_t)r * dim + i];
        m *= inv_rows;
        float sgm = 1.0f / (1.0f + expf(-m));
        int b = (int)(sgm * (float)(NBINS - 1));
        b = b < 0 ? 0 : (b > NBINS - 1 ? NBINS - 1 : b);

        float c[NBINS];
        #pragma unroll
        for (int j = 0; j < NBINS; ++j) c[j] = counts[(size_t)i * NBINS + j];
        float s = 0.0f;
        #pragma unroll
        for (int j = 0; j < NBINS; ++j) s += c[j];
        float inv  = 1.0f / fmaxf(s,        1e-8f);
        float invp = 1.0f / fmaxf(s + 1.0f, 1e-8f);
        float Hp = 0.0f, Hq = 0.0f;
        #pragma unroll
        for (int j = 0; j < NBINS; ++j) {
            float oh = (j == b) ? 1.0f : 0.0f;
            float p  = c[j] * inv;
            float pp = (c[j] + oh) * invp;
            float lp = __log2f(p  + 1e-10f);
            float lq = __log2f(pp + 1e-10f);
            Hp -= p * lp; Hq -= pp * lq;
            ig += pp * (lq - lp);
            out[(size_t)3 * dim + 2 + (size_t)i * NBINS + j] =
                fmaxf(c[j] * 0.95f + oh * 0.05f, 0.01f);
        }
        ig = fmaxf(ig, 0.0f);
        out[i] = ig;
        out[(size_t)dim     + 1 + i] = Hp;
        out[(size_t)2 * dim + 1 + i] = Hq;
    }

    // ---- deterministic block reduction of info_gain ----
    const unsigned FULL_M = 0xffffffffu;
    #pragma unroll
    for (int o = 16; o > 0; o >>= 1)
        ig += __shfl_down_sync(FULL_M, ig, o);

    __shared__ float ws[THREADS / 32];
    int lane = threadIdx.x & 31;
    int w    = threadIdx.x >> 5;
    if (lane == 0) ws[w] = ig;
    __syncthreads();
    if (w == 0) {
        float v = (lane < THREADS / 32) ? ws[lane] : 0.0f;
        #pragma unroll
        for (int o = 4; o > 0; o >>= 1)
            v += __shfl_down_sync(FULL_M, v, o);
        if (lane == 0) g_partials[blockIdx.x] = v;
    }

    // ---- last-block final reduction ----
    __shared__ bool is_last;
    __threadfence();
    if (threadIdx.x == 0) {
        unsigned ticket = atomicAdd(&g_counter, 1u);
        is_last = (ticket == (unsigned)(nblocks - 1));
    }
    __syncthreads();

    if (is_last) {
        __threadfence();
        __shared__ double sh[THREADS];
        double a = 0.0;
        for (int p = threadIdx.x; p < nblocks; p += THREADS)   // fixed order
            a += (double)g_partials[p];
        sh[threadIdx.x] = a;
        __syncthreads();
        #pragma unroll
        for (int o = THREADS / 2; o > 0; o >>= 1) {
            if (threadIdx.x < o) sh[threadIdx.x] += sh[threadIdx.x + o];
            __syncthreads();
        }
        if (threadIdx.x == 0) {
            float mean = (float)(sh[0] / (double)dim);
            out[dim] = mean;
            float z = mean * 50.0f - 1.0f;
            out[(size_t)3 * dim + 1] = 1.0f / (1.0f + expf(-z));
            g_counter = 0;   // reset for next graph replay
        }
    }
}

extern "C" void kernel_launch(void* const* d_in, const int* in_sizes, int n_in,
                              void* d_out, int out_size)
{
    const float* obs    = (const float*)d_in[0];
    const float* counts = (const float*)d_in[1];
    float* out = (float*)d_out;

    int dim  = in_sizes[1] / NBINS;
    int rows = in_sizes[0] / dim;
    int nb   = (dim + THREADS - 1) / THREADS;

    ep_fused_kernel<<<nb, THREADS>>>(obs, counts, out, dim, rows,
                                     1.0f / (float)rows, nb);
}